// round 15
// baseline (speedup 1.0000x reference)
#include <cuda_runtime.h>
#include <cuda_bf16.h>
#include <stdint.h>
#include <math.h>

#define Nn 50000
#define E_MAX 1600000
#define F_IN 256
#define HCC 128
#define NHEAD 4
#define CDIM 32
#define NG 64
#define NCLS 16
#define SB 512
#define NB ((Nn + SB - 1) / SB)   // 98
#define NSPLIT 25088

// ---------------- scratch (device globals; no allocation allowed) ----------
__device__ __nv_bfloat16 g_hb[(size_t)Nn * HCC];
__device__ __nv_bfloat16 g_hb2[(size_t)Nn * HCC];
__device__ float g_o[(size_t)Nn * HCC];
__device__ float g_as[Nn * NHEAD];
__device__ float g_ad[Nn * NHEAD];
__device__ float g_as2[Nn * NHEAD];
__device__ float g_ad2[Nn * NHEAD];
__device__ int   g_deg[Nn];
__device__ int   g_rank[E_MAX];
__device__ int   g_rowstart[Nn + 1];
__device__ int   g_csrc[E_MAX];
__device__ int   g_bsum[NB];
__device__ float g_pool[NG * HCC];
__device__ int   g_cnt[NG];
__device__ __nv_bfloat16 g_acat[(size_t)Nn * 2 * F_IN];
__device__ __nv_bfloat16 g_bcat[HCC * 2 * F_IN];
__device__ __nv_bfloat16 g_bcat2[HCC * 2 * HCC];

// ---------------- cp.async / ldmatrix helpers ----------------
__device__ __forceinline__ void cpa16(void* s, const void* g, int pred) {
    unsigned int sa = (unsigned int)__cvta_generic_to_shared(s);
    asm volatile(
        "{\n\t.reg .pred p;\n\t"
        "setp.ne.b32 p, %2, 0;\n\t"
        "@p cp.async.cg.shared.global [%0], [%1], 16;\n\t"
        "@!p cp.async.cg.shared.global [%0], [%1], 16, 0;\n\t}"
        :: "r"(sa), "l"(g), "r"(pred));
}
__device__ __forceinline__ void cpa16u(void* s, const void* g) {
    unsigned int sa = (unsigned int)__cvta_generic_to_shared(s);
    asm volatile("cp.async.cg.shared.global [%0], [%1], 16;" :: "r"(sa), "l"(g));
}
__device__ __forceinline__ void ldsm4(unsigned& r0, unsigned& r1, unsigned& r2,
                                      unsigned& r3, unsigned addr) {
    asm volatile("ldmatrix.sync.aligned.m8n8.x4.shared.b16 {%0,%1,%2,%3}, [%4];"
                 : "=r"(r0), "=r"(r1), "=r"(r2), "=r"(r3) : "r"(addr));
}

// ---------------- CSR build (rank-based, scatter atomic-free) --------------
__global__ void k_deg(const int* __restrict__ ei, int E) {
    int e4 = (blockIdx.x * blockDim.x + threadIdx.x) * 4;
    if (e4 >= E) return;
    if (e4 + 3 < E && ((E & 3) == 0)) {
        int4 d = *(const int4*)&ei[E + e4];
        int4 r;
        r.x = atomicAdd(&g_deg[d.x], 1);
        r.y = atomicAdd(&g_deg[d.y], 1);
        r.z = atomicAdd(&g_deg[d.z], 1);
        r.w = atomicAdd(&g_deg[d.w], 1);
        *(int4*)&g_rank[e4] = r;
    } else {
        for (int e = e4; e < min(e4 + 4, E); e++)
            g_rank[e] = atomicAdd(&g_deg[ei[E + e]], 1);
    }
}

__global__ void k_scanA() {
    __shared__ int s[SB];
    int t = threadIdx.x;
    int i = blockIdx.x * SB + t;
    int v = (i < Nn) ? g_deg[i] : 0;
    if (i < Nn) g_deg[i] = 0;
    s[t] = v;
    __syncthreads();
    for (int off = 1; off < SB; off <<= 1) {
        int x = (t >= off) ? s[t - off] : 0;
        __syncthreads();
        s[t] += x;
        __syncthreads();
    }
    if (i < Nn) g_rowstart[i] = s[t] - v;
    if (t == SB - 1) g_bsum[blockIdx.x] = s[t];
}

__global__ void k_scanB() {
    __shared__ int sb[NB];
    __shared__ int soff;
    int t = threadIdx.x;
    int b = blockIdx.x;
    int i = b * SB + t;
    if (t < NB) sb[t] = g_bsum[t];
    __syncthreads();
    if (t == 0) {
        int o = 0;
        for (int j = 0; j < b; j++) o += sb[j];
        soff = o;
    }
    __syncthreads();
    int off = soff;
    if (i < Nn) g_rowstart[i] += off;
    if (b == NB - 1 && t == 0) g_rowstart[Nn] = off + sb[b];
}

__global__ void k_scatter(const int* __restrict__ ei, int E) {
    int e4 = (blockIdx.x * blockDim.x + threadIdx.x) * 4;
    if (e4 >= E) return;
    if (e4 + 3 < E && ((E & 3) == 0)) {
        int4 s = *(const int4*)&ei[e4];
        int4 d = *(const int4*)&ei[E + e4];
        int4 r = *(const int4*)&g_rank[e4];
        g_csrc[g_rowstart[d.x] + r.x] = s.x;
        g_csrc[g_rowstart[d.y] + r.y] = s.y;
        g_csrc[g_rowstart[d.z] + r.z] = s.z;
        g_csrc[g_rowstart[d.w] + r.w] = s.w;
    } else {
        for (int e = e4; e < min(e4 + 4, E); e++)
            g_csrc[g_rowstart[ei[E + e]] + g_rank[e]] = ei[e];
    }
}

// ---------------- split prep (row-ranged; DOW adds weight splits) ----------
template <int DOW>
__global__ void k_prep(const float* __restrict__ x, const float* __restrict__ W1,
                       const float* __restrict__ W2, int rowBeg, int rowEnd) {
    int nrows = rowEnd - rowBeg;
    int nx = nrows * (F_IN / 2);
    int idx = blockIdx.x * blockDim.x + threadIdx.x;
    if (idx < nx) {
        int r = rowBeg + idx / (F_IN / 2);
        int c = (idx % (F_IN / 2)) * 2;
        float2 v = *(const float2*)&x[(size_t)r * F_IN + c];
        __nv_bfloat16 hx = __float2bfloat16(v.x);
        __nv_bfloat16 hy = __float2bfloat16(v.y);
        __nv_bfloat16 lx = __float2bfloat16(v.x - __bfloat162float(hx));
        __nv_bfloat16 ly = __float2bfloat16(v.y - __bfloat162float(hy));
        *(__nv_bfloat162*)&g_acat[(size_t)r * (2 * F_IN) + c] = __nv_bfloat162(hx, hy);
        *(__nv_bfloat162*)&g_acat[(size_t)r * (2 * F_IN) + F_IN + c] = __nv_bfloat162(lx, ly);
    } else if (DOW) {
        int j = idx - nx;
        if (j < F_IN * HCC) {
            int k = j / HCC;
            int n = j - k * HCC;
            float v = W1[j];
            __nv_bfloat16 h = __float2bfloat16(v);
            __nv_bfloat16 l = __float2bfloat16(v - __bfloat162float(h));
            g_bcat[(size_t)n * (2 * F_IN) + k] = h;
            g_bcat[(size_t)n * (2 * F_IN) + F_IN + k] = l;
        } else if (j < F_IN * HCC + HCC * HCC) {
            j -= F_IN * HCC;
            int k = j / HCC;
            int n = j - k * HCC;
            float v = W2[(size_t)k * HCC + n];
            __nv_bfloat16 h = __float2bfloat16(v);
            __nv_bfloat16 l = __float2bfloat16(v - __bfloat162float(h));
            g_bcat2[(size_t)n * (2 * HCC) + k] = h;
            g_bcat2[(size_t)n * (2 * HCC) + HCC + k] = l;
        }
    }
}

// ---------------- tensor-core GEMM (bf16x3, ldmatrix fragments) ------------
#define SA 72
#define STAGE_ELEMS (128 * SA)
template <int K>
__global__ void k_gemm_mma(const __nv_bfloat16* __restrict__ Bmat,
                           __nv_bfloat16* __restrict__ Cb, int M, int rowOff,
                           const float* __restrict__ atts,
                           const float* __restrict__ attd,
                           float* __restrict__ oas, float* __restrict__ oad) {
    extern __shared__ __nv_bfloat16 sm[];
    __nv_bfloat16* As = sm;
    __nv_bfloat16* Bs = sm + 2 * STAGE_ELEMS;
    const int tid = threadIdx.x;
    const int bm = rowOff + blockIdx.x * 128;
    const int lane = tid & 31;
    const int warp = tid >> 5;
    const int wm = (warp & 3) * 32;
    const int wn = (warp >> 2) * 64;
    const int g = lane >> 2;
    const int t = lane & 3;
    const int A2K = 2 * K;
    const int NK = (3 * K) / 64;

    int crow[4], cq[4], cvalid[4];
    const __nv_bfloat16* asrcp[4];
#pragma unroll
    for (int i = 0; i < 4; i++) {
        int lin = tid + 256 * i;
        crow[i] = lin >> 3;
        cq[i] = lin & 7;
        cvalid[i] = (bm + crow[i] < M) ? 1 : 0;
        int r = cvalid[i] ? (bm + crow[i]) : 0;
        asrcp[i] = &g_acat[(size_t)r * A2K];
    }

    const int li = lane & 7;
    const int seg = lane >> 3;
    const int aRow = (seg & 1) * 8 + li;
    const int aCol = (seg >> 1) * 8;
    unsigned aOff0 = ((wm + aRow) * SA + aCol) * 2;
    unsigned aOff1 = ((wm + 16 + aRow) * SA + aCol) * 2;
    const int bRow = (seg >> 1) * 8 + li;
    const int bCol = (seg & 1) * 8;
    unsigned bOff[4];
#pragma unroll
    for (int np = 0; np < 4; np++)
        bOff[np] = ((wn + np * 16 + bRow) * SA + bCol) * 2;

    const unsigned asBase = (unsigned)__cvta_generic_to_shared(As);
    const unsigned bsBase = (unsigned)__cvta_generic_to_shared(Bs);
    const unsigned stageBytes = STAGE_ELEMS * 2;

    float acc[2][8][4];
#pragma unroll
    for (int mt = 0; mt < 2; mt++)
#pragma unroll
        for (int nt = 0; nt < 8; nt++)
#pragma unroll
            for (int r = 0; r < 4; r++) acc[mt][nt][r] = 0.f;

    auto issue = [&](int it, int st) {
        int kb = it * 64;
        int asrc = (kb < 2 * K) ? kb : kb - 2 * K;
        int bsrc = (kb < K) ? kb : kb - K;
        __nv_bfloat16* ab = As + st * STAGE_ELEMS;
        __nv_bfloat16* bb = Bs + st * STAGE_ELEMS;
#pragma unroll
        for (int i = 0; i < 4; i++)
            cpa16(&ab[crow[i] * SA + cq[i] * 8], asrcp[i] + asrc + cq[i] * 8, cvalid[i]);
#pragma unroll
        for (int i = 0; i < 4; i++)
            cpa16u(&bb[crow[i] * SA + cq[i] * 8],
                   &Bmat[(size_t)crow[i] * A2K + bsrc + cq[i] * 8]);
        asm volatile("cp.async.commit_group;");
    };

    issue(0, 0);

    for (int it = 0; it < NK; it++) {
        if (it + 1 < NK) {
            issue(it + 1, (it + 1) & 1);
            asm volatile("cp.async.wait_group 1;");
        } else {
            asm volatile("cp.async.wait_group 0;");
        }
        __syncthreads();

        const unsigned aStage = asBase + (it & 1) * stageBytes;
        const unsigned bStage = bsBase + (it & 1) * stageBytes;
#pragma unroll
        for (int s = 0; s < 4; s++) {
            const unsigned sOff = s * 32;
            unsigned a[2][4], b[8][2];
            ldsm4(a[0][0], a[0][1], a[0][2], a[0][3], aStage + aOff0 + sOff);
            ldsm4(a[1][0], a[1][1], a[1][2], a[1][3], aStage + aOff1 + sOff);
#pragma unroll
            for (int np = 0; np < 4; np++)
                ldsm4(b[2 * np][0], b[2 * np][1], b[2 * np + 1][0], b[2 * np + 1][1],
                      bStage + bOff[np] + sOff);
#pragma unroll
            for (int mt = 0; mt < 2; mt++)
#pragma unroll
                for (int nt = 0; nt < 8; nt++) {
                    asm volatile(
                        "mma.sync.aligned.m16n8k16.row.col.f32.bf16.bf16.f32 "
                        "{%0,%1,%2,%3}, {%4,%5,%6,%7}, {%8,%9}, {%0,%1,%2,%3};"
                        : "+f"(acc[mt][nt][0]), "+f"(acc[mt][nt][1]),
                          "+f"(acc[mt][nt][2]), "+f"(acc[mt][nt][3])
                        : "r"(a[mt][0]), "r"(a[mt][1]), "r"(a[mt][2]), "r"(a[mt][3]),
                          "r"(b[nt][0]), "r"(b[nt][1]));
                }
        }
        __syncthreads();
    }

    float* sAs = (float*)sm;
    float* sAd = (float*)sm + 512;
    for (int i = tid; i < 1024; i += 256) ((float*)sm)[i] = 0.f;
    __syncthreads();

    const int hb0 = wn >> 5;
#pragma unroll
    for (int mt = 0; mt < 2; mt++) {
        int r0l = wm + mt * 16 + g;
        int row0 = bm + r0l;
        int row1 = row0 + 8;
        float s0[2] = {0.f, 0.f}, d0[2] = {0.f, 0.f};
        float s1[2] = {0.f, 0.f}, d1[2] = {0.f, 0.f};
#pragma unroll
        for (int nt = 0; nt < 8; nt++) {
            int c0 = wn + nt * 8 + 2 * t;
            int h = nt >> 2;
            float a0 = atts[c0], a1 = atts[c0 + 1];
            float b0 = attd[c0], b1 = attd[c0 + 1];
            s0[h] += acc[mt][nt][0] * a0 + acc[mt][nt][1] * a1;
            d0[h] += acc[mt][nt][0] * b0 + acc[mt][nt][1] * b1;
            s1[h] += acc[mt][nt][2] * a0 + acc[mt][nt][3] * a1;
            d1[h] += acc[mt][nt][2] * b0 + acc[mt][nt][3] * b1;
            if (row0 < M)
                *(__nv_bfloat162*)&Cb[(size_t)row0 * HCC + c0] =
                    __nv_bfloat162(__float2bfloat16(acc[mt][nt][0]),
                                   __float2bfloat16(acc[mt][nt][1]));
            if (row1 < M)
                *(__nv_bfloat162*)&Cb[(size_t)row1 * HCC + c0] =
                    __nv_bfloat162(__float2bfloat16(acc[mt][nt][2]),
                                   __float2bfloat16(acc[mt][nt][3]));
        }
#pragma unroll
        for (int h = 0; h < 2; h++) {
            atomicAdd(&sAs[r0l * 4 + hb0 + h], s0[h]);
            atomicAdd(&sAd[r0l * 4 + hb0 + h], d0[h]);
            atomicAdd(&sAs[(r0l + 8) * 4 + hb0 + h], s1[h]);
            atomicAdd(&sAd[(r0l + 8) * 4 + hb0 + h], d1[h]);
        }
    }
    __syncthreads();
    if (tid < 128 && bm + tid < M) {
        *(float4*)&oas[(size_t)(bm + tid) * 4] = *(float4*)&sAs[tid * 4];
        *(float4*)&oad[(size_t)(bm + tid) * 4] = *(float4*)&sAd[tid * 4];
    }
}

__device__ __forceinline__ float leaky(float v) { return fmaxf(v, 0.2f * v); }

__device__ __forceinline__ void bf8_to_f(uint4 u, float* f) {
    float2 a = __bfloat1622float2(*(const __nv_bfloat162*)&u.x);
    float2 b = __bfloat1622float2(*(const __nv_bfloat162*)&u.y);
    float2 c = __bfloat1622float2(*(const __nv_bfloat162*)&u.z);
    float2 d = __bfloat1622float2(*(const __nv_bfloat162*)&u.w);
    f[0] = a.x; f[1] = a.y; f[2] = b.x; f[3] = b.y;
    f[4] = c.x; f[5] = c.y; f[6] = d.x; f[7] = d.y;
}

// ---------------- half-warp online-softmax aggregation (R12 form) ----------
template <int SPLIT>
__global__ void __launch_bounds__(256) k_aggregate(
        const __nv_bfloat16* __restrict__ hb,
        const float* __restrict__ pas, const float* __restrict__ pad,
        const float* __restrict__ bias, float* __restrict__ out,
        int nodeOff, int nodeEnd) {
    int node = nodeOff + ((blockIdx.x * blockDim.x + threadIdx.x) >> 5);
    if (node >= nodeEnd) return;
    int lane = threadIdx.x & 31;
    int half = lane >> 4;
    int q = lane & 15;
    int head = q >> 2;
    unsigned hm = half ? 0xFFFF0000u : 0x0000FFFFu;

    float ad = pad[node * 4 + head];

    float m, z;
    float acc[8];
    if (half == 0) {
        float as_self = pas[node * 4 + head];
        m = leaky(as_self + ad);
        z = 1.f;
        uint4 hs = *(const uint4*)&hb[(size_t)node * HCC + q * 8];
        bf8_to_f(hs, acc);
    } else {
        m = -1e30f;
        z = 0.f;
#pragma unroll
        for (int i = 0; i < 8; i++) acc[i] = 0.f;
    }

    int beg = g_rowstart[node];
    int end = g_rowstart[node + 1];
    int base = half * 16;

    for (int j0 = beg; j0 < end; j0 += 32) {
        int cnt = min(32, end - j0);
        int myj = j0 + lane;
        int sj = (myj < end) ? g_csrc[myj] : 0;
        int cntH = min(max(cnt - base, 0), 16);

        int t = 0;
        for (; t + 4 <= cntH; t += 4) {
            int s0 = __shfl_sync(hm, sj, base + t);
            int s1 = __shfl_sync(hm, sj, base + t + 1);
            int s2 = __shfl_sync(hm, sj, base + t + 2);
            int s3 = __shfl_sync(hm, sj, base + t + 3);
            float a0 = pas[s0 * 4 + head];
            float a1 = pas[s1 * 4 + head];
            float a2 = pas[s2 * 4 + head];
            float a3 = pas[s3 * 4 + head];
            uint4 u0 = *(const uint4*)&hb[(size_t)s0 * HCC + q * 8];
            uint4 u1 = *(const uint4*)&hb[(size_t)s1 * HCC + q * 8];
            uint4 u2 = *(const uint4*)&hb[(size_t)s2 * HCC + q * 8];
            uint4 u3 = *(const uint4*)&hb[(size_t)s3 * HCC + q * 8];
            float e0 = leaky(a0 + ad);
            float e1 = leaky(a1 + ad);
            float e2 = leaky(a2 + ad);
            float e3 = leaky(a3 + ad);
            float em = fmaxf(fmaxf(e0, e1), fmaxf(e2, e3));
            if (em > m) {
                float sc = __expf(m - em);
                z *= sc;
#pragma unroll
                for (int i = 0; i < 8; i++) acc[i] *= sc;
                m = em;
            }
            float p0 = __expf(e0 - m);
            float p1 = __expf(e1 - m);
            float p2 = __expf(e2 - m);
            float p3 = __expf(e3 - m);
            z += (p0 + p1) + (p2 + p3);
            float h0[8], h1[8], h2[8], h3[8];
            bf8_to_f(u0, h0);
            bf8_to_f(u1, h1);
            bf8_to_f(u2, h2);
            bf8_to_f(u3, h3);
#pragma unroll
            for (int i = 0; i < 8; i++) {
                acc[i] = fmaf(p0, h0[i], acc[i]);
                acc[i] = fmaf(p1, h1[i], acc[i]);
                acc[i] = fmaf(p2, h2[i], acc[i]);
                acc[i] = fmaf(p3, h3[i], acc[i]);
            }
        }
        for (; t < cntH; t++) {
            int s = __shfl_sync(hm, sj, base + t);
            float a = pas[s * 4 + head];
            uint4 u = *(const uint4*)&hb[(size_t)s * HCC + q * 8];
            float e = leaky(a + ad);
            if (e > m) {
                float sc = __expf(m - e);
                z *= sc;
#pragma unroll
                for (int i = 0; i < 8; i++) acc[i] *= sc;
                m = e;
            }
            float p = __expf(e - m);
            z += p;
            float hh[8];
            bf8_to_f(u, hh);
#pragma unroll
            for (int i = 0; i < 8; i++) acc[i] = fmaf(p, hh[i], acc[i]);
        }
    }

    float m2 = __shfl_xor_sync(0xffffffffu, m, 16);
    float z2 = __shfl_xor_sync(0xffffffffu, z, 16);
    float mm = fmaxf(m, m2);
    float sc1 = __expf(m - mm);
    float sc2 = __expf(m2 - mm);
    z = z * sc1 + z2 * sc2;
#pragma unroll
    for (int i = 0; i < 8; i++) {
        float o2 = __shfl_xor_sync(0xffffffffu, acc[i], 16);
        acc[i] = acc[i] * sc1 + o2 * sc2;
    }

    float inv = 1.f / z;
    float4 b0 = *(const float4*)&bias[q * 8];
    float4 b1 = *(const float4*)&bias[q * 8 + 4];
    float o[8];
    o[0] = fmaxf(fmaf(acc[0], inv, b0.x), 0.f);
    o[1] = fmaxf(fmaf(acc[1], inv, b0.y), 0.f);
    o[2] = fmaxf(fmaf(acc[2], inv, b0.z), 0.f);
    o[3] = fmaxf(fmaf(acc[3], inv, b0.w), 0.f);
    o[4] = fmaxf(fmaf(acc[4], inv, b1.x), 0.f);
    o[5] = fmaxf(fmaf(acc[5], inv, b1.y), 0.f);
    o[6] = fmaxf(fmaf(acc[6], inv, b1.z), 0.f);
    o[7] = fmaxf(fmaf(acc[7], inv, b1.w), 0.f);

    if (SPLIT) {
        if (half == 0) {
            unsigned w[4];
#pragma unroll
            for (int i = 0; i < 4; i++) {
                __nv_bfloat162 v(__float2bfloat16(o[2 * i]), __float2bfloat16(o[2 * i + 1]));
                w[i] = *(unsigned*)&v;
            }
            *(uint4*)&g_acat[(size_t)node * 256 + q * 8] = make_uint4(w[0], w[1], w[2], w[3]);
        } else {
            unsigned w[4];
#pragma unroll
            for (int i = 0; i < 4; i++) {
                float x0 = o[2 * i], x1 = o[2 * i + 1];
                __nv_bfloat16 hx = __float2bfloat16(x0);
                __nv_bfloat16 hy = __float2bfloat16(x1);
                __nv_bfloat162 v(__float2bfloat16(x0 - __bfloat162float(hx)),
                                 __float2bfloat16(x1 - __bfloat162float(hy)));
                w[i] = *(unsigned*)&v;
            }
            *(uint4*)&g_acat[(size_t)node * 256 + 128 + q * 8] = make_uint4(w[0], w[1], w[2], w[3]);
        }
    } else {
        if (half == 0)
            *(float4*)&out[(size_t)node * HCC + q * 8] = make_float4(o[0], o[1], o[2], o[3]);
        else
            *(float4*)&out[(size_t)node * HCC + q * 8 + 4] = make_float4(o[4], o[5], o[6], o[7]);
    }
}

// ---------------- pooling (count fused, node-ranged) ----------------
__global__ void k_pool(const float* __restrict__ hf, const int* __restrict__ batch,
                       int nodeBeg, int nodeEnd) {
    __shared__ int sc[NG];
    int t = threadIdx.x;
    int n0 = nodeBeg + blockIdx.x * 64;
    if (n0 >= nodeEnd) return;
    int n1 = min(n0 + 64, nodeEnd);
    if (t < NG) sc[t] = 0;
    __syncthreads();
    if (t < 64 && n0 + t < n1) atomicAdd(&sc[batch[n0 + t]], 1);
    __syncthreads();
    if (t < NG && sc[t]) atomicAdd(&g_cnt[t], sc[t]);

    int cur = batch[n0];
    float acc = 0.f;
    for (int n = n0; n < n1; n++) {
        int bb = batch[n];
        if (bb != cur) {
            atomicAdd(&g_pool[cur * HCC + t], acc);
            acc = 0.f;
            cur = bb;
        }
        acc += hf[(size_t)n * HCC + t];
    }
    atomicAdd(&g_pool[cur * HCC + t], acc);
}

// ---------------- classifier (self-cleans g_pool/g_cnt) ----------------
__global__ void k_classifier(const float* __restrict__ Wc1, const float* __restrict__ bc1,
                             const float* __restrict__ Wc2, const float* __restrict__ bc2,
                             float* __restrict__ out) {
    int g = blockIdx.x;
    int t = threadIdx.x;
    __shared__ float sg[HCC];
    __shared__ float sg1[CDIM];
    float inv = 1.f / (float)g_cnt[g];
    for (int c = t; c < HCC; c += 32) sg[c] = g_pool[g * HCC + c] * inv;
    __syncthreads();
    for (int c = t; c < HCC; c += 32) g_pool[g * HCC + c] = 0.f;
    if (t == 0) g_cnt[g] = 0;
    float a = bc1[t];
#pragma unroll 4
    for (int k = 0; k < HCC; k++) a = fmaf(sg[k], Wc1[k * CDIM + t], a);
    sg1[t] = a;
    __syncthreads();
    if (t < NCLS) {
        float b = bc2[t];
#pragma unroll
        for (int k = 0; k < CDIM; k++) b = fmaf(sg1[k], Wc2[k * NCLS + t], b);
        out[g * NCLS + t] = 1.f / (1.f + expf(-b));
    }
}

// ---------------- launch ----------------
extern "C" void kernel_launch(void* const* d_in, const int* in_sizes, int n_in,
                              void* d_out, int out_size) {
    const float* x    = (const float*)d_in[0];
    const int*   ei   = (const int*)d_in[1];
    const int*   batch= (const int*)d_in[2];
    const float* W1   = (const float*)d_in[3];
    const float* as1  = (const float*)d_in[4];
    const float* ad1  = (const float*)d_in[5];
    const float* b1   = (const float*)d_in[6];
    const float* W2   = (const float*)d_in[7];
    const float* as2  = (const float*)d_in[8];
    const float* ad2  = (const float*)d_in[9];
    const float* b2   = (const float*)d_in[10];
    const float* Wc1  = (const float*)d_in[11];
    const float* bc1  = (const float*)d_in[12];
    const float* Wc2  = (const float*)d_in[13];
    const float* bc2  = (const float*)d_in[14];
    float* out = (float*)d_out;

    int E = in_sizes[1] / 2;
    if (E > E_MAX) E = E_MAX;

    float *oP, *asP, *adP, *as2P, *ad2P;
    __nv_bfloat16 *hbP, *hb2P, *bc1P, *bc2P;
    cudaGetSymbolAddress((void**)&oP, g_o);
    cudaGetSymbolAddress((void**)&hbP, g_hb);
    cudaGetSymbolAddress((void**)&hb2P, g_hb2);
    cudaGetSymbolAddress((void**)&asP, g_as);
    cudaGetSymbolAddress((void**)&adP, g_ad);
    cudaGetSymbolAddress((void**)&as2P, g_as2);
    cudaGetSymbolAddress((void**)&ad2P, g_ad2);
    cudaGetSymbolAddress((void**)&bc1P, g_bcat);
    cudaGetSymbolAddress((void**)&bc2P, g_bcat2);

    const int smemBytes = 4 * STAGE_ELEMS * (int)sizeof(__nv_bfloat16);

    static cudaStream_t s2 = 0, s3 = 0;
    static cudaEvent_t evF = 0, evP = 0, evJ = 0, evA = 0, evG = 0, evO = 0, evPl = 0;
    static int inited = 0;
    if (!inited) {
        cudaFuncSetAttribute(k_gemm_mma<F_IN>, cudaFuncAttributeMaxDynamicSharedMemorySize, smemBytes);
        cudaFuncSetAttribute(k_gemm_mma<HCC>, cudaFuncAttributeMaxDynamicSharedMemorySize, smemBytes);
        cudaStreamCreateWithFlags(&s2, cudaStreamNonBlocking);
        cudaStreamCreateWithFlags(&s3, cudaStreamNonBlocking);
        cudaEventCreateWithFlags(&evF, cudaEventDisableTiming);
        cudaEventCreateWithFlags(&evP, cudaEventDisableTiming);
        cudaEventCreateWithFlags(&evJ, cudaEventDisableTiming);
        cudaEventCreateWithFlags(&evA, cudaEventDisableTiming);
        cudaEventCreateWithFlags(&evG, cudaEventDisableTiming);
        cudaEventCreateWithFlags(&evO, cudaEventDisableTiming);
        cudaEventCreateWithFlags(&evPl, cudaEventDisableTiming);
        inited = 1;
    }

    int tpb = 256;
    int mmaBlocksA = NSPLIT / 128;                 // 196
    int mmaBlocksB = (Nn - NSPLIT + 127) / 128;    // 195
    int aggBlocksA = (NSPLIT * 32) / tpb;
    int aggBlocksB = ((Nn - NSPLIT) * 32 + tpb - 1) / tpb;
    int edge4Blocks = ((E + 3) / 4 + tpb - 1) / tpb;
    int prepABlocks = (NSPLIT * (F_IN / 2) + F_IN * HCC + HCC * HCC + tpb - 1) / tpb;
    int prepBBlocks = ((Nn - NSPLIT) * (F_IN / 2) + tpb - 1) / tpb;
    int poolABlocks = NSPLIT / 64;                 // 392
    int poolBBlocks = (Nn - NSPLIT + 63) / 64;

    // fork marker for captured side streams
    cudaEventRecord(evF, 0);
    cudaStreamWaitEvent(s2, evF, 0);
    cudaStreamWaitEvent(s3, evF, 0);

    // (1) prepA: x rows [0,NSPLIT) + weight splits
    k_prep<1><<<prepABlocks, tpb>>>(x, W1, W2, 0, NSPLIT);
    // (2) prepB on s3 concurrent with gemm1a
    k_prep<0><<<prepBBlocks, tpb, 0, s3>>>(x, W1, W2, NSPLIT, Nn);
    cudaEventRecord(evP, s3);
    // (3) gemm1a rows [0,NSPLIT)
    k_gemm_mma<F_IN><<<mmaBlocksA, 256, smemBytes>>>(bc1P, hbP, NSPLIT, 0, as1, ad1, asP, adP);
    // (4) gemm1b rows [NSPLIT,Nn)  <-- ncu capture slot
    cudaStreamWaitEvent(0, evP, 0);
    k_gemm_mma<F_IN><<<mmaBlocksB, 256, smemBytes>>>(bc1P, hbP, Nn, NSPLIT, as1, ad1, asP, adP);

    // (5-8) CSR build on s2 (independent; starts at t=0 in the graph)
    k_deg<<<edge4Blocks, tpb, 0, s2>>>(ei, E);
    k_scanA<<<NB, SB, 0, s2>>>();
    k_scanB<<<NB, SB, 0, s2>>>();
    k_scatter<<<edge4Blocks, tpb, 0, s2>>>(ei, E);
    cudaEventRecord(evJ, s2);

    // agg1 (needs full gemm1 + CSR); split for gemm2a overlap
    cudaStreamWaitEvent(0, evJ, 0);
    k_aggregate<1><<<aggBlocksA, tpb>>>(hbP, asP, adP, b1, oP, 0, NSPLIT);
    cudaEventRecord(evA, 0);
    k_aggregate<1><<<aggBlocksB, tpb>>>(hbP, asP, adP, b1, oP, NSPLIT, Nn);

    // gemm2a on s2 (rows [0,NSPLIT), needs agg1a output rows only)
    cudaStreamWaitEvent(s2, evA, 0);
    k_gemm_mma<HCC><<<mmaBlocksA, 256, smemBytes, s2>>>(bc2P, hb2P, NSPLIT, 0, as2, ad2, as2P, ad2P);
    cudaEventRecord(evG, s2);

    // gemm2b on main
    k_gemm_mma<HCC><<<mmaBlocksB, 256, smemBytes>>>(bc2P, hb2P, Nn, NSPLIT, as2, ad2, as2P, ad2P);

    // agg2 split; pool-a overlaps agg2b
    cudaStreamWaitEvent(0, evG, 0);
    k_aggregate<0><<<aggBlocksA, tpb>>>(hb2P, as2P, ad2P, b2, oP, 0, NSPLIT);
    cudaEventRecord(evO, 0);
    k_aggregate<0><<<aggBlocksB, tpb>>>(hb2P, as2P, ad2P, b2, oP, NSPLIT, Nn);

    cudaStreamWaitEvent(s3, evO, 0);
    k_pool<<<poolABlocks, HCC, 0, s3>>>(oP, batch, 0, NSPLIT);
    cudaEventRecord(evPl, s3);

    k_pool<<<poolBBlocks, HCC>>>(oP, batch, NSPLIT, Nn);
    cudaStreamWaitEvent(0, evPl, 0);
    k_classifier<<<NG, 32>>>(Wc1, bc1, Wc2, bc2, out);
}

// round 16
// speedup vs baseline: 1.0657x; 1.0657x over previous
#include <cuda_runtime.h>
#include <cuda_bf16.h>
#include <stdint.h>
#include <math.h>

#define Nn 50000
#define E_MAX 1600000
#define F_IN 256
#define HCC 128
#define NHEAD 4
#define CDIM 32
#define NG 64
#define NCLS 16
#define SB 512
#define NB ((Nn + SB - 1) / SB)   // 98
#define NSPLIT 25088

// ---------------- scratch (device globals; no allocation allowed) ----------
__device__ __nv_bfloat16 g_hb[(size_t)Nn * HCC];
__device__ __nv_bfloat16 g_hb2[(size_t)Nn * HCC];
__device__ float g_o[(size_t)Nn * HCC];
__device__ float g_as[Nn * NHEAD];
__device__ float g_ad[Nn * NHEAD];
__device__ float g_as2[Nn * NHEAD];
__device__ float g_ad2[Nn * NHEAD];
__device__ int   g_deg[Nn];
__device__ int   g_rank[E_MAX];
__device__ int   g_rowstart[Nn + 1];
__device__ int   g_csrc[E_MAX];
__device__ int   g_bsum[NB];
__device__ float g_pool[NG * HCC];
__device__ int   g_cnt[NG];
__device__ __nv_bfloat16 g_acat[(size_t)Nn * 2 * F_IN];
__device__ __nv_bfloat16 g_bcat[HCC * 2 * F_IN];
__device__ __nv_bfloat16 g_bcat2[HCC * 2 * HCC];

// ---------------- cp.async / ldmatrix helpers ----------------
__device__ __forceinline__ void cpa16(void* s, const void* g, int pred) {
    unsigned int sa = (unsigned int)__cvta_generic_to_shared(s);
    asm volatile(
        "{\n\t.reg .pred p;\n\t"
        "setp.ne.b32 p, %2, 0;\n\t"
        "@p cp.async.cg.shared.global [%0], [%1], 16;\n\t"
        "@!p cp.async.cg.shared.global [%0], [%1], 16, 0;\n\t}"
        :: "r"(sa), "l"(g), "r"(pred));
}
__device__ __forceinline__ void cpa16u(void* s, const void* g) {
    unsigned int sa = (unsigned int)__cvta_generic_to_shared(s);
    asm volatile("cp.async.cg.shared.global [%0], [%1], 16;" :: "r"(sa), "l"(g));
}
__device__ __forceinline__ void ldsm4(unsigned& r0, unsigned& r1, unsigned& r2,
                                      unsigned& r3, unsigned addr) {
    asm volatile("ldmatrix.sync.aligned.m8n8.x4.shared.b16 {%0,%1,%2,%3}, [%4];"
                 : "=r"(r0), "=r"(r1), "=r"(r2), "=r"(r3) : "r"(addr));
}

// ---------------- CSR build (rank-based, scatter atomic-free) --------------
__global__ void k_deg(const int* __restrict__ ei, int E) {
    int e4 = (blockIdx.x * blockDim.x + threadIdx.x) * 4;
    if (e4 >= E) return;
    if (e4 + 3 < E && ((E & 3) == 0)) {
        int4 d = *(const int4*)&ei[E + e4];
        int4 r;
        r.x = atomicAdd(&g_deg[d.x], 1);
        r.y = atomicAdd(&g_deg[d.y], 1);
        r.z = atomicAdd(&g_deg[d.z], 1);
        r.w = atomicAdd(&g_deg[d.w], 1);
        *(int4*)&g_rank[e4] = r;
    } else {
        for (int e = e4; e < min(e4 + 4, E); e++)
            g_rank[e] = atomicAdd(&g_deg[ei[E + e]], 1);
    }
}

__global__ void k_scanA() {
    __shared__ int s[SB];
    int t = threadIdx.x;
    int i = blockIdx.x * SB + t;
    int v = (i < Nn) ? g_deg[i] : 0;
    if (i < Nn) g_deg[i] = 0;
    s[t] = v;
    __syncthreads();
    for (int off = 1; off < SB; off <<= 1) {
        int x = (t >= off) ? s[t - off] : 0;
        __syncthreads();
        s[t] += x;
        __syncthreads();
    }
    if (i < Nn) g_rowstart[i] = s[t] - v;
    if (t == SB - 1) g_bsum[blockIdx.x] = s[t];
}

__global__ void k_scanB() {
    __shared__ int sb[NB];
    __shared__ int soff;
    int t = threadIdx.x;
    int b = blockIdx.x;
    int i = b * SB + t;
    if (t < NB) sb[t] = g_bsum[t];
    __syncthreads();
    if (t == 0) {
        int o = 0;
        for (int j = 0; j < b; j++) o += sb[j];
        soff = o;
    }
    __syncthreads();
    int off = soff;
    if (i < Nn) g_rowstart[i] += off;
    if (b == NB - 1 && t == 0) g_rowstart[Nn] = off + sb[b];
}

__global__ void k_scatter(const int* __restrict__ ei, int E) {
    int e4 = (blockIdx.x * blockDim.x + threadIdx.x) * 4;
    if (e4 >= E) return;
    if (e4 + 3 < E && ((E & 3) == 0)) {
        int4 s = *(const int4*)&ei[e4];
        int4 d = *(const int4*)&ei[E + e4];
        int4 r = *(const int4*)&g_rank[e4];
        g_csrc[g_rowstart[d.x] + r.x] = s.x;
        g_csrc[g_rowstart[d.y] + r.y] = s.y;
        g_csrc[g_rowstart[d.z] + r.z] = s.z;
        g_csrc[g_rowstart[d.w] + r.w] = s.w;
    } else {
        for (int e = e4; e < min(e4 + 4, E); e++)
            g_csrc[g_rowstart[ei[E + e]] + g_rank[e]] = ei[e];
    }
}

// ---------------- fused split prep ----------------
#define NA_PREP (Nn * (F_IN / 2))
__global__ void k_prep(const float* __restrict__ x, const float* __restrict__ W1,
                       const float* __restrict__ W2) {
    int idx = blockIdx.x * blockDim.x + threadIdx.x;
    if (idx < NA_PREP) {
        int r = idx / (F_IN / 2);
        int c = (idx - r * (F_IN / 2)) * 2;
        float2 v = *(const float2*)&x[(size_t)r * F_IN + c];
        __nv_bfloat16 hx = __float2bfloat16(v.x);
        __nv_bfloat16 hy = __float2bfloat16(v.y);
        __nv_bfloat16 lx = __float2bfloat16(v.x - __bfloat162float(hx));
        __nv_bfloat16 ly = __float2bfloat16(v.y - __bfloat162float(hy));
        *(__nv_bfloat162*)&g_acat[(size_t)r * (2 * F_IN) + c] = __nv_bfloat162(hx, hy);
        *(__nv_bfloat162*)&g_acat[(size_t)r * (2 * F_IN) + F_IN + c] = __nv_bfloat162(lx, ly);
    } else if (idx < NA_PREP + F_IN * HCC) {
        int j = idx - NA_PREP;
        int k = j / HCC;
        int n = j - k * HCC;
        float v = W1[j];
        __nv_bfloat16 h = __float2bfloat16(v);
        __nv_bfloat16 l = __float2bfloat16(v - __bfloat162float(h));
        g_bcat[(size_t)n * (2 * F_IN) + k] = h;
        g_bcat[(size_t)n * (2 * F_IN) + F_IN + k] = l;
    } else if (idx < NA_PREP + F_IN * HCC + HCC * HCC) {
        int j = idx - NA_PREP - F_IN * HCC;
        int k = j / HCC;
        int n = j - k * HCC;
        float v = W2[j];
        __nv_bfloat16 h = __float2bfloat16(v);
        __nv_bfloat16 l = __float2bfloat16(v - __bfloat162float(h));
        g_bcat2[(size_t)n * (2 * HCC) + k] = h;
        g_bcat2[(size_t)n * (2 * HCC) + HCC + k] = l;
    }
}

// ---------------- tensor-core GEMM (bf16x3, ldmatrix fragments) ------------
#define SA 72
#define STAGE_ELEMS (128 * SA)
template <int K>
__global__ void k_gemm_mma(const __nv_bfloat16* __restrict__ Bmat,
                           __nv_bfloat16* __restrict__ Cb, int M, int rowOff,
                           const float* __restrict__ atts,
                           const float* __restrict__ attd,
                           float* __restrict__ oas, float* __restrict__ oad) {
    extern __shared__ __nv_bfloat16 sm[];
    __nv_bfloat16* As = sm;
    __nv_bfloat16* Bs = sm + 2 * STAGE_ELEMS;
    const int tid = threadIdx.x;
    const int bm = rowOff + blockIdx.x * 128;
    const int lane = tid & 31;
    const int warp = tid >> 5;
    const int wm = (warp & 3) * 32;
    const int wn = (warp >> 2) * 64;
    const int g = lane >> 2;
    const int t = lane & 3;
    const int A2K = 2 * K;
    const int NK = (3 * K) / 64;

    int crow[4], cq[4], cvalid[4];
    const __nv_bfloat16* asrcp[4];
#pragma unroll
    for (int i = 0; i < 4; i++) {
        int lin = tid + 256 * i;
        crow[i] = lin >> 3;
        cq[i] = lin & 7;
        cvalid[i] = (bm + crow[i] < M) ? 1 : 0;
        int r = cvalid[i] ? (bm + crow[i]) : 0;
        asrcp[i] = &g_acat[(size_t)r * A2K];
    }

    const int li = lane & 7;
    const int seg = lane >> 3;
    const int aRow = (seg & 1) * 8 + li;
    const int aCol = (seg >> 1) * 8;
    unsigned aOff0 = ((wm + aRow) * SA + aCol) * 2;
    unsigned aOff1 = ((wm + 16 + aRow) * SA + aCol) * 2;
    const int bRow = (seg >> 1) * 8 + li;
    const int bCol = (seg & 1) * 8;
    unsigned bOff[4];
#pragma unroll
    for (int np = 0; np < 4; np++)
        bOff[np] = ((wn + np * 16 + bRow) * SA + bCol) * 2;

    const unsigned asBase = (unsigned)__cvta_generic_to_shared(As);
    const unsigned bsBase = (unsigned)__cvta_generic_to_shared(Bs);
    const unsigned stageBytes = STAGE_ELEMS * 2;

    float acc[2][8][4];
#pragma unroll
    for (int mt = 0; mt < 2; mt++)
#pragma unroll
        for (int nt = 0; nt < 8; nt++)
#pragma unroll
            for (int r = 0; r < 4; r++) acc[mt][nt][r] = 0.f;

    auto issue = [&](int it, int st) {
        int kb = it * 64;
        int asrc = (kb < 2 * K) ? kb : kb - 2 * K;
        int bsrc = (kb < K) ? kb : kb - K;
        __nv_bfloat16* ab = As + st * STAGE_ELEMS;
        __nv_bfloat16* bb = Bs + st * STAGE_ELEMS;
#pragma unroll
        for (int i = 0; i < 4; i++)
            cpa16(&ab[crow[i] * SA + cq[i] * 8], asrcp[i] + asrc + cq[i] * 8, cvalid[i]);
#pragma unroll
        for (int i = 0; i < 4; i++)
            cpa16u(&bb[crow[i] * SA + cq[i] * 8],
                   &Bmat[(size_t)crow[i] * A2K + bsrc + cq[i] * 8]);
        asm volatile("cp.async.commit_group;");
    };

    issue(0, 0);

    for (int it = 0; it < NK; it++) {
        if (it + 1 < NK) {
            issue(it + 1, (it + 1) & 1);
            asm volatile("cp.async.wait_group 1;");
        } else {
            asm volatile("cp.async.wait_group 0;");
        }
        __syncthreads();

        const unsigned aStage = asBase + (it & 1) * stageBytes;
        const unsigned bStage = bsBase + (it & 1) * stageBytes;
#pragma unroll
        for (int s = 0; s < 4; s++) {
            const unsigned sOff = s * 32;
            unsigned a[2][4], b[8][2];
            ldsm4(a[0][0], a[0][1], a[0][2], a[0][3], aStage + aOff0 + sOff);
            ldsm4(a[1][0], a[1][1], a[1][2], a[1][3], aStage + aOff1 + sOff);
#pragma unroll
            for (int np = 0; np < 4; np++)
                ldsm4(b[2 * np][0], b[2 * np][1], b[2 * np + 1][0], b[2 * np + 1][1],
                      bStage + bOff[np] + sOff);
#pragma unroll
            for (int mt = 0; mt < 2; mt++)
#pragma unroll
                for (int nt = 0; nt < 8; nt++) {
                    asm volatile(
                        "mma.sync.aligned.m16n8k16.row.col.f32.bf16.bf16.f32 "
                        "{%0,%1,%2,%3}, {%4,%5,%6,%7}, {%8,%9}, {%0,%1,%2,%3};"
                        : "+f"(acc[mt][nt][0]), "+f"(acc[mt][nt][1]),
                          "+f"(acc[mt][nt][2]), "+f"(acc[mt][nt][3])
                        : "r"(a[mt][0]), "r"(a[mt][1]), "r"(a[mt][2]), "r"(a[mt][3]),
                          "r"(b[nt][0]), "r"(b[nt][1]));
                }
        }
        __syncthreads();
    }

    float* sAs = (float*)sm;
    float* sAd = (float*)sm + 512;
    for (int i = tid; i < 1024; i += 256) ((float*)sm)[i] = 0.f;
    __syncthreads();

    const int hb0 = wn >> 5;
#pragma unroll
    for (int mt = 0; mt < 2; mt++) {
        int r0l = wm + mt * 16 + g;
        int row0 = bm + r0l;
        int row1 = row0 + 8;
        float s0[2] = {0.f, 0.f}, d0[2] = {0.f, 0.f};
        float s1[2] = {0.f, 0.f}, d1[2] = {0.f, 0.f};
#pragma unroll
        for (int nt = 0; nt < 8; nt++) {
            int c0 = wn + nt * 8 + 2 * t;
            int h = nt >> 2;
            float a0 = atts[c0], a1 = atts[c0 + 1];
            float b0 = attd[c0], b1 = attd[c0 + 1];
            s0[h] += acc[mt][nt][0] * a0 + acc[mt][nt][1] * a1;
            d0[h] += acc[mt][nt][0] * b0 + acc[mt][nt][1] * b1;
            s1[h] += acc[mt][nt][2] * a0 + acc[mt][nt][3] * a1;
            d1[h] += acc[mt][nt][2] * b0 + acc[mt][nt][3] * b1;
            if (row0 < M)
                *(__nv_bfloat162*)&Cb[(size_t)row0 * HCC + c0] =
                    __nv_bfloat162(__float2bfloat16(acc[mt][nt][0]),
                                   __float2bfloat16(acc[mt][nt][1]));
            if (row1 < M)
                *(__nv_bfloat162*)&Cb[(size_t)row1 * HCC + c0] =
                    __nv_bfloat162(__float2bfloat16(acc[mt][nt][2]),
                                   __float2bfloat16(acc[mt][nt][3]));
        }
#pragma unroll
        for (int h = 0; h < 2; h++) {
            atomicAdd(&sAs[r0l * 4 + hb0 + h], s0[h]);
            atomicAdd(&sAd[r0l * 4 + hb0 + h], d0[h]);
            atomicAdd(&sAs[(r0l + 8) * 4 + hb0 + h], s1[h]);
            atomicAdd(&sAd[(r0l + 8) * 4 + hb0 + h], d1[h]);
        }
    }
    __syncthreads();
    if (tid < 128 && bm + tid < M) {
        *(float4*)&oas[(size_t)(bm + tid) * 4] = *(float4*)&sAs[tid * 4];
        *(float4*)&oad[(size_t)(bm + tid) * 4] = *(float4*)&sAd[tid * 4];
    }
}

__device__ __forceinline__ float leaky(float v) { return fmaxf(v, 0.2f * v); }

__device__ __forceinline__ void bf8_to_f(uint4 u, float* f) {
    float2 a = __bfloat1622float2(*(const __nv_bfloat162*)&u.x);
    float2 b = __bfloat1622float2(*(const __nv_bfloat162*)&u.y);
    float2 c = __bfloat1622float2(*(const __nv_bfloat162*)&u.z);
    float2 d = __bfloat1622float2(*(const __nv_bfloat162*)&u.w);
    f[0] = a.x; f[1] = a.y; f[2] = b.x; f[3] = b.y;
    f[4] = c.x; f[5] = c.y; f[6] = d.x; f[7] = d.y;
}

// ---------------- half-warp online-softmax aggregation (R12 form) ----------
template <int SPLIT>
__global__ void __launch_bounds__(256) k_aggregate(
        const __nv_bfloat16* __restrict__ hb,
        const float* __restrict__ pas, const float* __restrict__ pad,
        const float* __restrict__ bias, float* __restrict__ out,
        int nodeOff, int nodeEnd) {
    int node = nodeOff + ((blockIdx.x * blockDim.x + threadIdx.x) >> 5);
    if (node >= nodeEnd) return;
    int lane = threadIdx.x & 31;
    int half = lane >> 4;
    int q = lane & 15;
    int head = q >> 2;
    unsigned hm = half ? 0xFFFF0000u : 0x0000FFFFu;

    float ad = pad[node * 4 + head];

    float m, z;
    float acc[8];
    if (half == 0) {
        float as_self = pas[node * 4 + head];
        m = leaky(as_self + ad);
        z = 1.f;
        uint4 hs = *(const uint4*)&hb[(size_t)node * HCC + q * 8];
        bf8_to_f(hs, acc);
    } else {
        m = -1e30f;
        z = 0.f;
#pragma unroll
        for (int i = 0; i < 8; i++) acc[i] = 0.f;
    }

    int beg = g_rowstart[node];
    int end = g_rowstart[node + 1];
    int base = half * 16;

    for (int j0 = beg; j0 < end; j0 += 32) {
        int cnt = min(32, end - j0);
        int myj = j0 + lane;
        int sj = (myj < end) ? g_csrc[myj] : 0;
        int cntH = min(max(cnt - base, 0), 16);

        int t = 0;
        for (; t + 4 <= cntH; t += 4) {
            int s0 = __shfl_sync(hm, sj, base + t);
            int s1 = __shfl_sync(hm, sj, base + t + 1);
            int s2 = __shfl_sync(hm, sj, base + t + 2);
            int s3 = __shfl_sync(hm, sj, base + t + 3);
            float a0 = pas[s0 * 4 + head];
            float a1 = pas[s1 * 4 + head];
            float a2 = pas[s2 * 4 + head];
            float a3 = pas[s3 * 4 + head];
            uint4 u0 = *(const uint4*)&hb[(size_t)s0 * HCC + q * 8];
            uint4 u1 = *(const uint4*)&hb[(size_t)s1 * HCC + q * 8];
            uint4 u2 = *(const uint4*)&hb[(size_t)s2 * HCC + q * 8];
            uint4 u3 = *(const uint4*)&hb[(size_t)s3 * HCC + q * 8];
            float e0 = leaky(a0 + ad);
            float e1 = leaky(a1 + ad);
            float e2 = leaky(a2 + ad);
            float e3 = leaky(a3 + ad);
            float em = fmaxf(fmaxf(e0, e1), fmaxf(e2, e3));
            if (em > m) {
                float sc = __expf(m - em);
                z *= sc;
#pragma unroll
                for (int i = 0; i < 8; i++) acc[i] *= sc;
                m = em;
            }
            float p0 = __expf(e0 - m);
            float p1 = __expf(e1 - m);
            float p2 = __expf(e2 - m);
            float p3 = __expf(e3 - m);
            z += (p0 + p1) + (p2 + p3);
            float h0[8], h1[8], h2[8], h3[8];
            bf8_to_f(u0, h0);
            bf8_to_f(u1, h1);
            bf8_to_f(u2, h2);
            bf8_to_f(u3, h3);
#pragma unroll
            for (int i = 0; i < 8; i++) {
                acc[i] = fmaf(p0, h0[i], acc[i]);
                acc[i] = fmaf(p1, h1[i], acc[i]);
                acc[i] = fmaf(p2, h2[i], acc[i]);
                acc[i] = fmaf(p3, h3[i], acc[i]);
            }
        }
        for (; t < cntH; t++) {
            int s = __shfl_sync(hm, sj, base + t);
            float a = pas[s * 4 + head];
            uint4 u = *(const uint4*)&hb[(size_t)s * HCC + q * 8];
            float e = leaky(a + ad);
            if (e > m) {
                float sc = __expf(m - e);
                z *= sc;
#pragma unroll
                for (int i = 0; i < 8; i++) acc[i] *= sc;
                m = e;
            }
            float p = __expf(e - m);
            z += p;
            float hh[8];
            bf8_to_f(u, hh);
#pragma unroll
            for (int i = 0; i < 8; i++) acc[i] = fmaf(p, hh[i], acc[i]);
        }
    }

    float m2 = __shfl_xor_sync(0xffffffffu, m, 16);
    float z2 = __shfl_xor_sync(0xffffffffu, z, 16);
    float mm = fmaxf(m, m2);
    float sc1 = __expf(m - mm);
    float sc2 = __expf(m2 - mm);
    z = z * sc1 + z2 * sc2;
#pragma unroll
    for (int i = 0; i < 8; i++) {
        float o2 = __shfl_xor_sync(0xffffffffu, acc[i], 16);
        acc[i] = acc[i] * sc1 + o2 * sc2;
    }

    float inv = 1.f / z;
    float4 b0 = *(const float4*)&bias[q * 8];
    float4 b1 = *(const float4*)&bias[q * 8 + 4];
    float o[8];
    o[0] = fmaxf(fmaf(acc[0], inv, b0.x), 0.f);
    o[1] = fmaxf(fmaf(acc[1], inv, b0.y), 0.f);
    o[2] = fmaxf(fmaf(acc[2], inv, b0.z), 0.f);
    o[3] = fmaxf(fmaf(acc[3], inv, b0.w), 0.f);
    o[4] = fmaxf(fmaf(acc[4], inv, b1.x), 0.f);
    o[5] = fmaxf(fmaf(acc[5], inv, b1.y), 0.f);
    o[6] = fmaxf(fmaf(acc[6], inv, b1.z), 0.f);
    o[7] = fmaxf(fmaf(acc[7], inv, b1.w), 0.f);

    if (SPLIT) {
        if (half == 0) {
            unsigned w[4];
#pragma unroll
            for (int i = 0; i < 4; i++) {
                __nv_bfloat162 v(__float2bfloat16(o[2 * i]), __float2bfloat16(o[2 * i + 1]));
                w[i] = *(unsigned*)&v;
            }
            *(uint4*)&g_acat[(size_t)node * 256 + q * 8] = make_uint4(w[0], w[1], w[2], w[3]);
        } else {
            unsigned w[4];
#pragma unroll
            for (int i = 0; i < 4; i++) {
                float x0 = o[2 * i], x1 = o[2 * i + 1];
                __nv_bfloat16 hx = __float2bfloat16(x0);
                __nv_bfloat16 hy = __float2bfloat16(x1);
                __nv_bfloat162 v(__float2bfloat16(x0 - __bfloat162float(hx)),
                                 __float2bfloat16(x1 - __bfloat162float(hy)));
                w[i] = *(unsigned*)&v;
            }
            *(uint4*)&g_acat[(size_t)node * 256 + 128 + q * 8] = make_uint4(w[0], w[1], w[2], w[3]);
        }
    } else {
        if (half == 0)
            *(float4*)&out[(size_t)node * HCC + q * 8] = make_float4(o[0], o[1], o[2], o[3]);
        else
            *(float4*)&out[(size_t)node * HCC + q * 8 + 4] = make_float4(o[4], o[5], o[6], o[7]);
    }
}

// ---------------- pooling (count fused) ----------------
__global__ void k_pool(const float* __restrict__ hf, const int* __restrict__ batch) {
    __shared__ int sc[NG];
    int t = threadIdx.x;
    int n0 = blockIdx.x * 64;
    if (n0 >= Nn) return;
    int n1 = min(n0 + 64, Nn);
    if (t < NG) sc[t] = 0;
    __syncthreads();
    if (t < 64 && n0 + t < n1) atomicAdd(&sc[batch[n0 + t]], 1);
    __syncthreads();
    if (t < NG && sc[t]) atomicAdd(&g_cnt[t], sc[t]);

    int cur = batch[n0];
    float acc = 0.f;
    for (int n = n0; n < n1; n++) {
        int bb = batch[n];
        if (bb != cur) {
            atomicAdd(&g_pool[cur * HCC + t], acc);
            acc = 0.f;
            cur = bb;
        }
        acc += hf[(size_t)n * HCC + t];
    }
    atomicAdd(&g_pool[cur * HCC + t], acc);
}

// ---------------- classifier (self-cleans g_pool/g_cnt) ----------------
__global__ void k_classifier(const float* __restrict__ Wc1, const float* __restrict__ bc1,
                             const float* __restrict__ Wc2, const float* __restrict__ bc2,
                             float* __restrict__ out) {
    int g = blockIdx.x;
    int t = threadIdx.x;
    __shared__ float sg[HCC];
    __shared__ float sg1[CDIM];
    float inv = 1.f / (float)g_cnt[g];
    for (int c = t; c < HCC; c += 32) sg[c] = g_pool[g * HCC + c] * inv;
    __syncthreads();
    for (int c = t; c < HCC; c += 32) g_pool[g * HCC + c] = 0.f;
    if (t == 0) g_cnt[g] = 0;
    float a = bc1[t];
#pragma unroll 4
    for (int k = 0; k < HCC; k++) a = fmaf(sg[k], Wc1[k * CDIM + t], a);
    sg1[t] = a;
    __syncthreads();
    if (t < NCLS) {
        float b = bc2[t];
#pragma unroll
        for (int k = 0; k < CDIM; k++) b = fmaf(sg1[k], Wc2[k * NCLS + t], b);
        out[g * NCLS + t] = 1.f / (1.f + expf(-b));
    }
}

// ---------------- launch ----------------
extern "C" void kernel_launch(void* const* d_in, const int* in_sizes, int n_in,
                              void* d_out, int out_size) {
    const float* x    = (const float*)d_in[0];
    const int*   ei   = (const int*)d_in[1];
    const int*   batch= (const int*)d_in[2];
    const float* W1   = (const float*)d_in[3];
    const float* as1  = (const float*)d_in[4];
    const float* ad1  = (const float*)d_in[5];
    const float* b1   = (const float*)d_in[6];
    const float* W2   = (const float*)d_in[7];
    const float* as2  = (const float*)d_in[8];
    const float* ad2  = (const float*)d_in[9];
    const float* b2   = (const float*)d_in[10];
    const float* Wc1  = (const float*)d_in[11];
    const float* bc1  = (const float*)d_in[12];
    const float* Wc2  = (const float*)d_in[13];
    const float* bc2  = (const float*)d_in[14];
    float* out = (float*)d_out;

    int E = in_sizes[1] / 2;
    if (E > E_MAX) E = E_MAX;

    float *oP, *asP, *adP, *as2P, *ad2P;
    __nv_bfloat16 *hbP, *hb2P, *bc1P, *bc2P;
    cudaGetSymbolAddress((void**)&oP, g_o);
    cudaGetSymbolAddress((void**)&hbP, g_hb);
    cudaGetSymbolAddress((void**)&hb2P, g_hb2);
    cudaGetSymbolAddress((void**)&asP, g_as);
    cudaGetSymbolAddress((void**)&adP, g_ad);
    cudaGetSymbolAddress((void**)&as2P, g_as2);
    cudaGetSymbolAddress((void**)&ad2P, g_ad2);
    cudaGetSymbolAddress((void**)&bc1P, g_bcat);
    cudaGetSymbolAddress((void**)&bc2P, g_bcat2);

    const int smemBytes = 4 * STAGE_ELEMS * (int)sizeof(__nv_bfloat16);

    static cudaStream_t s2 = 0;
    static cudaEvent_t evF = 0, evJ = 0, evA = 0, evG = 0;
    static int inited = 0;
    if (!inited) {
        cudaFuncSetAttribute(k_gemm_mma<F_IN>, cudaFuncAttributeMaxDynamicSharedMemorySize, smemBytes);
        cudaFuncSetAttribute(k_gemm_mma<HCC>, cudaFuncAttributeMaxDynamicSharedMemorySize, smemBytes);
        cudaStreamCreateWithFlags(&s2, cudaStreamNonBlocking);
        cudaEventCreateWithFlags(&evF, cudaEventDisableTiming);
        cudaEventCreateWithFlags(&evJ, cudaEventDisableTiming);
        cudaEventCreateWithFlags(&evA, cudaEventDisableTiming);
        cudaEventCreateWithFlags(&evG, cudaEventDisableTiming);
        inited = 1;
    }

    int tpb = 256;
    int mmaBlocksFull = (Nn + 127) / 128;
    int mmaBlocksA = NSPLIT / 128;
    int mmaBlocksB = (Nn - NSPLIT + 127) / 128;
    int aggBlocksA = (NSPLIT * 32) / tpb;
    int aggBlocksB = ((Nn - NSPLIT) * 32 + tpb - 1) / tpb;
    int aggBlocksFull = (Nn * 32 + tpb - 1) / tpb;
    int edge4Blocks = ((E + 3) / 4 + tpb - 1) / tpb;
    int prepBlocks = (NA_PREP + F_IN * HCC + HCC * HCC + tpb - 1) / tpb;

    cudaEventRecord(evF, 0);
    cudaStreamWaitEvent(s2, evF, 0);
    k_deg<<<edge4Blocks, tpb, 0, s2>>>(ei, E);
    k_scanA<<<NB, SB, 0, s2>>>();
    k_scanB<<<NB, SB, 0, s2>>>();
    k_scatter<<<edge4Blocks, tpb, 0, s2>>>(ei, E);
    cudaEventRecord(evJ, s2);

    k_prep<<<prepBlocks, tpb>>>(x, W1, W2);
    k_gemm_mma<F_IN><<<mmaBlocksFull, 256, smemBytes>>>(bc1P, hbP, Nn, 0, as1, ad1, asP, adP);

    cudaStreamWaitEvent(0, evJ, 0);

    k_aggregate<1><<<aggBlocksA, tpb>>>(hbP, asP, adP, b1, oP, 0, NSPLIT);
    cudaEventRecord(evA, 0);
    k_aggregate<1><<<aggBlocksB, tpb>>>(hbP, asP, adP, b1, oP, NSPLIT, Nn);

    cudaStreamWaitEvent(s2, evA, 0);
    k_gemm_mma<HCC><<<mmaBlocksA, 256, smemBytes, s2>>>(bc2P, hb2P, NSPLIT, 0, as2, ad2, as2P, ad2P);
    cudaEventRecord(evG, s2);

    k_gemm_mma<HCC><<<mmaBlocksB, 256, smemBytes>>>(bc2P, hb2P, Nn, NSPLIT, as2, ad2, as2P, ad2P);

    cudaStreamWaitEvent(0, evG, 0);
    k_aggregate<0><<<aggBlocksFull, tpb>>>(hb2P, as2P, ad2P, b2, oP, 0, Nn);

    k_pool<<<(Nn + 63) / 64, HCC>>>(oP, batch);
    k_classifier<<<NG, 32>>>(Wc1, bc1, Wc2, bc2, out);
}